// round 1
// baseline (speedup 1.0000x reference)
#include <cuda_runtime.h>
#include <math.h>

#define N_TOK 2048
#define C_DIM 1024
#define NHEAD 8
#define HD    128
#define NGRP  32
#define HW    64   // 8*8 spatial elems per (n,c)

// ---------------- scratch (device globals: allocation-free) ----------------
__device__ float g_feat[N_TOK * C_DIM];        // 8 MB  (feat, then LN'd in place)
__device__ float g_qkv [N_TOK * 3 * C_DIM];    // 24 MB
__device__ float g_attn[N_TOK * C_DIM];        // 8 MB
__device__ float g_coef[N_TOK * C_DIM];        // 8 MB  (valid ? gamma*out : 0)
__device__ int   g_bidx[N_TOK];
__device__ int   g_cnt [NGRP];
__device__ int   g_list[NGRP * N_TOK];

// ---------------- 0) batch_indices: detect int32 vs int64, canonicalize ----
__global__ void k_convert(const int* __restrict__ raw) {
    __shared__ int s64;
    if (threadIdx.x == 0) {
        int acc = 0;
        #pragma unroll
        for (int i = 0; i < 32; i++) acc |= raw[2 * i + 1];
        s64 = (acc == 0);   // int64 little-endian: high words of [0,32) values are 0
    }
    __syncthreads();
    int i = blockIdx.x * blockDim.x + threadIdx.x;
    if (i < N_TOK) g_bidx[i] = s64 ? raw[2 * i] : raw[i];
}

// ---------------- 1) deterministic group lists + counts --------------------
__global__ void k_groups() {
    __shared__ int sb[N_TOK];
    for (int i = threadIdx.x; i < N_TOK; i += blockDim.x) sb[i] = g_bidx[i];
    __syncthreads();
    int i = blockIdx.x * blockDim.x + threadIdx.x;   // grid 8 x 256 == 2048
    int b = sb[i];
    int pos = 0;
    for (int j = 0; j < i; j++) pos += (sb[j] == b) ? 1 : 0;
    g_list[b * N_TOK + pos] = i;
    if (blockIdx.x == 0 && threadIdx.x < NGRP) {
        int c = 0;
        for (int j = 0; j < N_TOK; j++) c += (sb[j] == (int)threadIdx.x) ? 1 : 0;
        g_cnt[threadIdx.x] = c;
    }
}

// ---------------- 2) feat = mean over H*W (warp per (n,c) row) -------------
__global__ void k_mean(const float* __restrict__ x) {
    int wid  = (blockIdx.x * blockDim.x + threadIdx.x) >> 5;
    int lane = threadIdx.x & 31;
    int row0 = wid * 4;                      // 4 rows per warp
    #pragma unroll
    for (int r = 0; r < 4; r++) {
        int row = row0 + r;
        float2 v = ((const float2*)x)[(size_t)row * 32 + lane];  // 64 floats/row
        float s = v.x + v.y;
        #pragma unroll
        for (int off = 16; off; off >>= 1) s += __shfl_xor_sync(0xffffffffu, s, off);
        if (lane == 0) g_feat[row] = s * (1.0f / 64.0f);
    }
}

// ---------------- 3) LayerNorm over C, in place ----------------------------
__global__ void k_ln(const float* __restrict__ w, const float* __restrict__ b) {
    int row = blockIdx.x, tid = threadIdx.x;
    int lane = tid & 31, warp = tid >> 5;
    float4 v = ((const float4*)g_feat)[row * 256 + tid];
    float s  = v.x + v.y + v.z + v.w;
    float sq = v.x * v.x + v.y * v.y + v.z * v.z + v.w * v.w;
    #pragma unroll
    for (int off = 16; off; off >>= 1) {
        s  += __shfl_xor_sync(0xffffffffu, s,  off);
        sq += __shfl_xor_sync(0xffffffffu, sq, off);
    }
    __shared__ float rs[8], rq[8];
    if (lane == 0) { rs[warp] = s; rq[warp] = sq; }
    __syncthreads();
    float S = 0.f, SQ = 0.f;
    #pragma unroll
    for (int i = 0; i < 8; i++) { S += rs[i]; SQ += rq[i]; }
    float mu   = S * (1.0f / C_DIM);
    float var  = SQ * (1.0f / C_DIM) - mu * mu;
    float rstd = rsqrtf(var + 1e-5f);
    float4 wv = ((const float4*)w)[tid], bv = ((const float4*)b)[tid];
    v.x = (v.x - mu) * rstd * wv.x + bv.x;
    v.y = (v.y - mu) * rstd * wv.y + bv.y;
    v.z = (v.z - mu) * rstd * wv.z + bv.z;
    v.w = (v.w - mu) * rstd * wv.w + bv.w;
    ((float4*)g_feat)[row * 256 + tid] = v;
}

// ---------------- 4) SGEMM: C[M,N] = A[M,K] * B[N,K]^T + bias --------------
// mode 0: plain (+bias). mode 1: epilogue coef = valid ? gamma*val : 0
__global__ void k_sgemm_bt(const float* __restrict__ A, const float* __restrict__ B,
                           const float* __restrict__ bias, float* __restrict__ C,
                           int M, int N, int K, int mode, const float* __restrict__ gamma) {
    __shared__ float As[16][64];
    __shared__ float Bs[16][64];
    const int tid = threadIdx.x;
    const int tx = tid & 15;        // col group (4 cols)
    const int ty = tid >> 4;        // row group (4 rows)
    const int lr = tid >> 2;        // 0..63 load row
    const int lk = tid & 3;         // 0..3  load k-float4
    const float* Ap = A + (size_t)(blockIdx.y * 64 + lr) * K + lk * 4;
    const float* Bp = B + (size_t)(blockIdx.x * 64 + lr) * K + lk * 4;
    float acc[4][4];
    #pragma unroll
    for (int i = 0; i < 4; i++)
        #pragma unroll
        for (int j = 0; j < 4; j++) acc[i][j] = 0.f;

    for (int k0 = 0; k0 < K; k0 += 16) {
        float4 a  = *(const float4*)(Ap + k0);
        float4 bq = *(const float4*)(Bp + k0);
        __syncthreads();
        As[lk * 4 + 0][lr] = a.x;  As[lk * 4 + 1][lr] = a.y;
        As[lk * 4 + 2][lr] = a.z;  As[lk * 4 + 3][lr] = a.w;
        Bs[lk * 4 + 0][lr] = bq.x; Bs[lk * 4 + 1][lr] = bq.y;
        Bs[lk * 4 + 2][lr] = bq.z; Bs[lk * 4 + 3][lr] = bq.w;
        __syncthreads();
        #pragma unroll
        for (int kk = 0; kk < 16; kk++) {
            float av[4], bv[4];
            *(float4*)av = *(const float4*)&As[kk][ty * 4];
            *(float4*)bv = *(const float4*)&Bs[kk][tx * 4];
            #pragma unroll
            for (int i = 0; i < 4; i++)
                #pragma unroll
                for (int j = 0; j < 4; j++) acc[i][j] += av[i] * bv[j];
        }
    }
    int row = blockIdx.y * 64 + ty * 4;
    int col = blockIdx.x * 64 + tx * 4;
    float4 bb = *(const float4*)&bias[col];
    #pragma unroll
    for (int i = 0; i < 4; i++) {
        float4 o;
        o.x = acc[i][0] + bb.x; o.y = acc[i][1] + bb.y;
        o.z = acc[i][2] + bb.z; o.w = acc[i][3] + bb.w;
        if (mode == 1) {
            int n = row + i;
            float gmul = (g_cnt[g_bidx[n]] > 1) ? gamma[0] : 0.0f;
            o.x *= gmul; o.y *= gmul; o.z *= gmul; o.w *= gmul;
        }
        *(float4*)&C[(size_t)(row + i) * N + col] = o;
    }
}

// ---------------- 5) per-(head,group) flash attention ----------------------
// grid = NHEAD * NGRP * QCH blocks (QCH=32, 64 queries each); 256 threads.
#define QCH 32
__global__ void k_attn() {
    int bx = blockIdx.x;
    int qc = bx & (QCH - 1);
    int g  = (bx >> 5) & (NGRP - 1);
    int h  = bx >> 10;
    int m  = g_cnt[g];
    int q0 = qc * 64;
    if (q0 >= m) return;

    int tid = threadIdx.x, w = tid >> 5, lane = tid & 31;
    __shared__ float Ks[32][HD];
    __shared__ float Vs[32][HD];

    float q[8][4], acc[8][4], mx[8], l[8];
    int   tok[8];
    #pragma unroll
    for (int t = 0; t < 8; t++) {
        int qi = q0 + w * 8 + t;
        if (qi < m) {
            tok[t] = g_list[g * N_TOK + qi];
            float4 qv = *(const float4*)&g_qkv[(size_t)tok[t] * 3072 + h * HD + lane * 4];
            q[t][0] = qv.x; q[t][1] = qv.y; q[t][2] = qv.z; q[t][3] = qv.w;
        } else tok[t] = -1;
        mx[t] = -1e30f; l[t] = 0.f;
        acc[t][0] = acc[t][1] = acc[t][2] = acc[t][3] = 0.f;
    }

    int ntile = (m + 31) >> 5;
    for (int kt = 0; kt < ntile; kt++) {
        int kbase = kt * 32;
        // cooperative K/V tile load: 32 keys x 128 floats each
        #pragma unroll
        for (int it = 0; it < 4; it++) {
            int p  = tid + it * 256;          // 0..1023 float4 slots
            int j  = p >> 5, c4 = p & 31;
            int kj = kbase + j;
            float4 kv = {0,0,0,0}, vv = {0,0,0,0};
            if (kj < m) {
                int ktok = g_list[g * N_TOK + kj];
                const float4* b4 = (const float4*)&g_qkv[(size_t)ktok * 3072];
                kv = b4[256 + h * 32 + c4];   // K block (offset C)
                vv = b4[512 + h * 32 + c4];   // V block (offset 2C)
            }
            *(float4*)&Ks[j][c4 * 4] = kv;
            *(float4*)&Vs[j][c4 * 4] = vv;
        }
        __syncthreads();

        int jmax = m - kbase; if (jmax > 32) jmax = 32;
        for (int j = 0; j < jmax; j++) {
            float4 kj4 = *(const float4*)&Ks[j][lane * 4];
            float4 vj4 = *(const float4*)&Vs[j][lane * 4];
            #pragma unroll
            for (int t = 0; t < 8; t++) {
                if (tok[t] < 0) continue;
                float s = q[t][0] * kj4.x + q[t][1] * kj4.y
                        + q[t][2] * kj4.z + q[t][3] * kj4.w;
                #pragma unroll
                for (int off = 16; off; off >>= 1) s += __shfl_xor_sync(0xffffffffu, s, off);
                s *= 0.08838834764831845f;   // 1/sqrt(128)
                if (s <= mx[t]) {
                    float p = __expf(s - mx[t]);
                    l[t] += p;
                    acc[t][0] += p * vj4.x; acc[t][1] += p * vj4.y;
                    acc[t][2] += p * vj4.z; acc[t][3] += p * vj4.w;
                } else {
                    float corr = __expf(mx[t] - s);
                    l[t] = l[t] * corr + 1.0f;
                    acc[t][0] = acc[t][0] * corr + vj4.x;
                    acc[t][1] = acc[t][1] * corr + vj4.y;
                    acc[t][2] = acc[t][2] * corr + vj4.z;
                    acc[t][3] = acc[t][3] * corr + vj4.w;
                    mx[t] = s;
                }
            }
        }
        __syncthreads();
    }

    #pragma unroll
    for (int t = 0; t < 8; t++) {
        if (tok[t] < 0) continue;
        float inv = 1.0f / l[t];
        float4 o = { acc[t][0] * inv, acc[t][1] * inv, acc[t][2] * inv, acc[t][3] * inv };
        *(float4*)&g_attn[(size_t)tok[t] * C_DIM + h * HD + lane * 4] = o;
    }
}

// ---------------- 6) y = x + coef[n,c] broadcast over HW -------------------
__global__ void k_add(const float* __restrict__ x, float* __restrict__ y) {
    const float4* x4 = (const float4*)x;
    float4* y4 = (float4*)y;
    const int total = N_TOK * C_DIM * (HW / 4);   // 33,554,432 float4
    int stride = gridDim.x * blockDim.x;
    for (int i = blockIdx.x * blockDim.x + threadIdx.x; i < total; i += stride) {
        float c = g_coef[i >> 4];                 // 16 float4 per (n,c) row
        float4 v = x4[i];
        v.x += c; v.y += c; v.z += c; v.w += c;
        y4[i] = v;
    }
}

// ---------------- launch ---------------------------------------------------
extern "C" void kernel_launch(void* const* d_in, const int* in_sizes, int n_in,
                              void* d_out, int out_size) {
    const float* x          = (const float*)d_in[0];
    const int*   braw       = (const int*)  d_in[1];   // int32 or int64 (detected)
    const float* ln_w       = (const float*)d_in[2];
    const float* ln_b       = (const float*)d_in[3];
    const float* in_proj_w  = (const float*)d_in[4];
    const float* in_proj_b  = (const float*)d_in[5];
    const float* out_proj_w = (const float*)d_in[6];
    const float* out_proj_b = (const float*)d_in[7];
    const float* gamma      = (const float*)d_in[8];
    float* y = (float*)d_out;

    float *p_feat, *p_qkv, *p_attn, *p_coef;
    cudaGetSymbolAddress((void**)&p_feat, g_feat);
    cudaGetSymbolAddress((void**)&p_qkv,  g_qkv);
    cudaGetSymbolAddress((void**)&p_attn, g_attn);
    cudaGetSymbolAddress((void**)&p_coef, g_coef);

    k_convert<<<8, 256>>>(braw);
    k_groups <<<8, 256>>>();
    k_mean   <<<65536, 256>>>(x);                       // 2M rows, warp/row, 4 rows/warp
    k_ln     <<<N_TOK, 256>>>(ln_w, ln_b);
    k_sgemm_bt<<<dim3(48, 32), 256>>>(p_feat, in_proj_w, in_proj_b, p_qkv,
                                      N_TOK, 3 * C_DIM, C_DIM, 0, nullptr);
    k_attn   <<<NHEAD * NGRP * QCH, 256>>>();
    k_sgemm_bt<<<dim3(16, 32), 256>>>(p_attn, out_proj_w, out_proj_b, p_coef,
                                      N_TOK, C_DIM, C_DIM, 1, gamma);
    k_add    <<<32768, 256>>>(x, y);
}

// round 4
// speedup vs baseline: 1.6636x; 1.6636x over previous
#include <cuda_runtime.h>
#include <cuda_fp16.h>
#include <stdint.h>
#include <math.h>

#define N_TOK 2048
#define C_DIM 1024
#define NHEAD 8
#define HD    128
#define NGRP  32
#define HW    64
#define PAD   40   // smem row stride in halfs (80B, multiple of 16B, conflict-free)

// ---------------- scratch (device globals: allocation-free) ----------------
__device__ float g_feat[N_TOK * C_DIM];
__device__ float g_qkv [N_TOK * 3 * C_DIM];
__device__ float g_coef[N_TOK * C_DIM];
__device__ int   g_bidx[N_TOK];
__device__ int   g_cnt [NGRP];
__device__ int   g_list[NGRP * N_TOK];
// fp16 operands: activations split hi/lo, weights single fp16
__device__ __half g_fh [N_TOK * C_DIM], g_fl [N_TOK * C_DIM];
__device__ __half g_wq [3 * C_DIM * C_DIM];
__device__ __half g_wo [C_DIM * C_DIM];
__device__ __half g_ah [N_TOK * C_DIM], g_al [N_TOK * C_DIM];

__device__ __forceinline__ uint32_t smem_u32(const void* p) {
    uint32_t a;
    asm("{ .reg .u64 t; cvta.to.shared.u64 t, %1; cvt.u32.u64 %0, t; }" : "=r"(a) : "l"(p));
    return a;
}

// ---------------- 0) batch_indices: detect int32 vs int64 ------------------
__global__ void k_convert(const int* __restrict__ raw) {
    __shared__ int s64;
    if (threadIdx.x == 0) {
        int acc = 0;
        #pragma unroll
        for (int i = 0; i < 32; i++) acc |= raw[2 * i + 1];
        s64 = (acc == 0);
    }
    __syncthreads();
    int i = blockIdx.x * blockDim.x + threadIdx.x;
    if (i < N_TOK) g_bidx[i] = s64 ? raw[2 * i] : raw[i];
}

// ---------------- 1) deterministic group lists + counts --------------------
__global__ void k_groups() {
    __shared__ int sb[N_TOK];
    for (int i = threadIdx.x; i < N_TOK; i += blockDim.x) sb[i] = g_bidx[i];
    __syncthreads();
    int i = blockIdx.x * blockDim.x + threadIdx.x;
    int b = sb[i];
    int pos = 0;
    for (int j = 0; j < i; j++) pos += (sb[j] == b) ? 1 : 0;
    g_list[b * N_TOK + pos] = i;
    if (blockIdx.x == 0 && threadIdx.x < NGRP) {
        int c = 0;
        for (int j = 0; j < N_TOK; j++) c += (sb[j] == (int)threadIdx.x) ? 1 : 0;
        g_cnt[threadIdx.x] = c;
    }
}

// ---------------- 2) feat = mean over H*W ----------------------------------
__global__ void k_mean(const float* __restrict__ x) {
    int wid  = (blockIdx.x * blockDim.x + threadIdx.x) >> 5;
    int lane = threadIdx.x & 31;
    int row0 = wid * 4;
    #pragma unroll
    for (int r = 0; r < 4; r++) {
        int row = row0 + r;
        float2 v = ((const float2*)x)[(size_t)row * 32 + lane];
        float s = v.x + v.y;
        #pragma unroll
        for (int off = 16; off; off >>= 1) s += __shfl_xor_sync(0xffffffffu, s, off);
        if (lane == 0) g_feat[row] = s * (1.0f / 64.0f);
    }
}

// ---------------- 3) LayerNorm over C, emit fp16 hi/lo ---------------------
__global__ void k_ln(const float* __restrict__ w, const float* __restrict__ b) {
    int row = blockIdx.x, tid = threadIdx.x;
    int lane = tid & 31, warp = tid >> 5;
    float4 v = ((const float4*)g_feat)[row * 256 + tid];
    float s  = v.x + v.y + v.z + v.w;
    float sq = v.x * v.x + v.y * v.y + v.z * v.z + v.w * v.w;
    #pragma unroll
    for (int off = 16; off; off >>= 1) {
        s  += __shfl_xor_sync(0xffffffffu, s,  off);
        sq += __shfl_xor_sync(0xffffffffu, sq, off);
    }
    __shared__ float rs[8], rq[8];
    if (lane == 0) { rs[warp] = s; rq[warp] = sq; }
    __syncthreads();
    float S = 0.f, SQ = 0.f;
    #pragma unroll
    for (int i = 0; i < 8; i++) { S += rs[i]; SQ += rq[i]; }
    float mu   = S * (1.0f / C_DIM);
    float var  = SQ * (1.0f / C_DIM) - mu * mu;
    float rstd = rsqrtf(var + 1e-5f);
    float4 wv = ((const float4*)w)[tid], bv = ((const float4*)b)[tid];
    float a[4];
    a[0] = (v.x - mu) * rstd * wv.x + bv.x;
    a[1] = (v.y - mu) * rstd * wv.y + bv.y;
    a[2] = (v.z - mu) * rstd * wv.z + bv.z;
    a[3] = (v.w - mu) * rstd * wv.w + bv.w;
    __half hs[4], ls[4];
    #pragma unroll
    for (int j = 0; j < 4; j++) {
        hs[j] = __float2half_rn(a[j]);
        ls[j] = __float2half_rn(a[j] - __half2float(hs[j]));
    }
    *(uint2*)&g_fh[row * C_DIM + tid * 4] = *(uint2*)hs;
    *(uint2*)&g_fl[row * C_DIM + tid * 4] = *(uint2*)ls;
}

// ---------------- 3b) fp32 -> fp16 (weights) -------------------------------
__global__ void k_half(const float* __restrict__ src, __half* __restrict__ dst, int n4) {
    int i = blockIdx.x * blockDim.x + threadIdx.x;
    if (i >= n4) return;
    float4 v = ((const float4*)src)[i];
    __half hs[4] = { __float2half_rn(v.x), __float2half_rn(v.y),
                     __float2half_rn(v.z), __float2half_rn(v.w) };
    *(uint2*)&dst[i * 4] = *(uint2*)hs;
}

// ---------------- 4) HMMA GEMM: C[M,N] = (Ah+Al)[M,K] * B[N,K]^T + bias ----
// Block 128x128, 8 warps (2x4), warp tile 64x32, k-chunk 32, K=1024.
// mode 1 epilogue: coef = valid ? gamma*(acc+bias) : 0
__global__ void __launch_bounds__(256)
k_hgemm(const __half* __restrict__ Ah, const __half* __restrict__ Al,
        const __half* __restrict__ B, const float* __restrict__ bias,
        float* __restrict__ C, int Ncols, int mode, const float* __restrict__ gamma) {
    __shared__ __align__(16) __half sAh[128 * PAD];
    __shared__ __align__(16) __half sAl[128 * PAD];
    __shared__ __align__(16) __half sB [128 * PAD];

    const int tid = threadIdx.x, warp = tid >> 5, lane = tid & 31;
    const int wm = warp >> 2, wn = warp & 3;       // 2 x 4 warp grid
    const int bM = blockIdx.y * 128, bN = blockIdx.x * 128;

    float acc[4][4][4];
    #pragma unroll
    for (int i = 0; i < 4; i++)
        #pragma unroll
        for (int j = 0; j < 4; j++)
            #pragma unroll
            for (int c = 0; c < 4; c++) acc[i][j][c] = 0.f;

    // loader indices: 512 uint4 per matrix (128 rows x 4), 2 per thread
    const int lr0 = tid >> 2, lc0 = (tid & 3) * 8;          // pass 0
    const int lr1 = (tid + 256) >> 2, lc1 = ((tid + 256) & 3) * 8;

    // ldmatrix lane addressing
    const int a_row = lane & 15, a_k = (lane >> 4) * 8;                 // A x4
    const int b_row = (lane & 7) + ((lane >> 4) << 3);                  // B x4
    const int b_k   = ((lane >> 3) & 1) * 8;

    const uint32_t sAh_b = smem_u32(sAh), sAl_b = smem_u32(sAl), sB_b = smem_u32(sB);

    for (int k0 = 0; k0 < C_DIM; k0 += 32) {
        __syncthreads();
        // load Ah, Al, B chunks (each 128 x 32 halfs)
        {
            size_t ga0 = (size_t)(bM + lr0) * C_DIM + k0 + lc0;
            size_t ga1 = (size_t)(bM + lr1) * C_DIM + k0 + lc1;
            size_t gb0 = (size_t)(bN + lr0) * C_DIM + k0 + lc0;
            size_t gb1 = (size_t)(bN + lr1) * C_DIM + k0 + lc1;
            *(uint4*)&sAh[lr0 * PAD + lc0] = *(const uint4*)&Ah[ga0];
            *(uint4*)&sAh[lr1 * PAD + lc1] = *(const uint4*)&Ah[ga1];
            *(uint4*)&sAl[lr0 * PAD + lc0] = *(const uint4*)&Al[ga0];
            *(uint4*)&sAl[lr1 * PAD + lc1] = *(const uint4*)&Al[ga1];
            *(uint4*)&sB [lr0 * PAD + lc0] = *(const uint4*)&B[gb0];
            *(uint4*)&sB [lr1 * PAD + lc1] = *(const uint4*)&B[gb1];
        }
        __syncthreads();

        #pragma unroll
        for (int ks = 0; ks < 32; ks += 16) {
            uint32_t aH[4][4], aL[4][4], bF[4][2];
            #pragma unroll
            for (int i = 0; i < 4; i++) {
                uint32_t off = (uint32_t)((wm * 64 + i * 16 + a_row) * PAD + ks + a_k) * 2;
                asm volatile("ldmatrix.sync.aligned.m8n8.x4.shared.b16 {%0,%1,%2,%3}, [%4];"
                    : "=r"(aH[i][0]), "=r"(aH[i][1]), "=r"(aH[i][2]), "=r"(aH[i][3])
                    : "r"(sAh_b + off));
                asm volatile("ldmatrix.sync.aligned.m8n8.x4.shared.b16 {%0,%1,%2,%3}, [%4];"
                    : "=r"(aL[i][0]), "=r"(aL[i][1]), "=r"(aL[i][2]), "=r"(aL[i][3])
                    : "r"(sAl_b + off));
            }
            #pragma unroll
            for (int jj = 0; jj < 2; jj++) {
                uint32_t off = (uint32_t)((wn * 32 + jj * 16 + b_row) * PAD + ks + b_k) * 2;
                uint32_t r0, r1, r2, r3;
                asm volatile("ldmatrix.sync.aligned.m8n8.x4.shared.b16 {%0,%1,%2,%3}, [%4];"
                    : "=r"(r0), "=r"(r1), "=r"(r2), "=r"(r3) : "r"(sB_b + off));
                bF[jj * 2 + 0][0] = r0; bF[jj * 2 + 0][1] = r1;
                bF[jj * 2 + 1][0] = r2; bF[jj * 2 + 1][1] = r3;
            }
            #pragma unroll
            for (int i = 0; i < 4; i++)
                #pragma unroll
                for (int j = 0; j < 4; j++) {
                    asm volatile(
                        "mma.sync.aligned.m16n8k16.row.col.f32.f16.f16.f32 "
                        "{%0,%1,%2,%3}, {%4,%5,%6,%7}, {%8,%9}, {%0,%1,%2,%3};"
                        : "+f"(acc[i][j][0]), "+f"(acc[i][j][1]),
                          "+f"(acc[i][j][2]), "+f"(acc[i][j][3])
                        : "r"(aH[i][0]), "r"(aH[i][1]), "r"(aH[i][2]), "r"(aH[i][3]),
                          "r"(bF[j][0]), "r"(bF[j][1]));
                    asm volatile(
                        "mma.sync.aligned.m16n8k16.row.col.f32.f16.f16.f32 "
                        "{%0,%1,%2,%3}, {%4,%5,%6,%7}, {%8,%9}, {%0,%1,%2,%3};"
                        : "+f"(acc[i][j][0]), "+f"(acc[i][j][1]),
                          "+f"(acc[i][j][2]), "+f"(acc[i][j][3])
                        : "r"(aL[i][0]), "r"(aL[i][1]), "r"(aL[i][2]), "r"(aL[i][3]),
                          "r"(bF[j][0]), "r"(bF[j][1]));
                }
        }
    }

    // epilogue
    const int g4 = lane >> 2, t4 = lane & 3;
    #pragma unroll
    for (int i = 0; i < 4; i++) {
        int r0 = bM + wm * 64 + i * 16 + g4;
        int r1 = r0 + 8;
        float gm0 = 1.f, gm1 = 1.f;
        if (mode == 1) {
            gm0 = (g_cnt[g_bidx[r0]] > 1) ? gamma[0] : 0.0f;
            gm1 = (g_cnt[g_bidx[r1]] > 1) ? gamma[0] : 0.0f;
        }
        #pragma unroll
        for (int j = 0; j < 4; j++) {
            int c = bN + wn * 32 + j * 8 + 2 * t4;
            float b0 = bias[c], b1 = bias[c + 1];
            float2 o0 = { (acc[i][j][0] + b0) * gm0, (acc[i][j][1] + b1) * gm0 };
            float2 o1 = { (acc[i][j][2] + b0) * gm1, (acc[i][j][3] + b1) * gm1 };
            *(float2*)&C[(size_t)r0 * Ncols + c] = o0;
            *(float2*)&C[(size_t)r1 * Ncols + c] = o1;
        }
    }
}

// ---------------- 5) per-(head,group) flash attention ----------------------
#define QCH 32
__global__ void k_attn() {
    int bx = blockIdx.x;
    int qc = bx & (QCH - 1);
    int g  = (bx >> 5) & (NGRP - 1);
    int h  = bx >> 10;
    int m  = g_cnt[g];
    int q0 = qc * 64;
    if (q0 >= m) return;

    int tid = threadIdx.x, w = tid >> 5, lane = tid & 31;
    __shared__ float Ks[32][HD];
    __shared__ float Vs[32][HD];

    float q[8][4], acc[8][4], mx[8], l[8];
    int   tok[8];
    #pragma unroll
    for (int t = 0; t < 8; t++) {
        int qi = q0 + w * 8 + t;
        if (qi < m) {
            tok[t] = g_list[g * N_TOK + qi];
            float4 qv = *(const float4*)&g_qkv[(size_t)tok[t] * 3072 + h * HD + lane * 4];
            q[t][0] = qv.x; q[t][1] = qv.y; q[t][2] = qv.z; q[t][3] = qv.w;
        } else tok[t] = -1;
        mx[t] = -1e30f; l[t] = 0.f;
        acc[t][0] = acc[t][1] = acc[t][2] = acc[t][3] = 0.f;
    }

    int ntile = (m + 31) >> 5;
    for (int kt = 0; kt < ntile; kt++) {
        int kbase = kt * 32;
        #pragma unroll
        for (int it = 0; it < 4; it++) {
            int p  = tid + it * 256;
            int j  = p >> 5, c4 = p & 31;
            int kj = kbase + j;
            float4 kv = {0,0,0,0}, vv = {0,0,0,0};
            if (kj < m) {
                int ktok = g_list[g * N_TOK + kj];
                const float4* b4 = (const float4*)&g_qkv[(size_t)ktok * 3072];
                kv = b4[256 + h * 32 + c4];
                vv = b4[512 + h * 32 + c4];
            }
            *(float4*)&Ks[j][c4 * 4] = kv;
            *(float4*)&Vs[j][c4 * 4] = vv;
        }
        __syncthreads();

        int jmax = m - kbase; if (jmax > 32) jmax = 32;
        for (int j = 0; j < jmax; j++) {
            float4 kj4 = *(const float4*)&Ks[j][lane * 4];
            float4 vj4 = *(const float4*)&Vs[j][lane * 4];
            #pragma unroll
            for (int t = 0; t < 8; t++) {
                if (tok[t] < 0) continue;
                float s = q[t][0] * kj4.x + q[t][1] * kj4.y
                        + q[t][2] * kj4.z + q[t][3] * kj4.w;
                #pragma unroll
                for (int off = 16; off; off >>= 1) s += __shfl_xor_sync(0xffffffffu, s, off);
                s *= 0.08838834764831845f;
                if (s <= mx[t]) {
                    float p = __expf(s - mx[t]);
                    l[t] += p;
                    acc[t][0] += p * vj4.x; acc[t][1] += p * vj4.y;
                    acc[t][2] += p * vj4.z; acc[t][3] += p * vj4.w;
                } else {
                    float corr = __expf(mx[t] - s);
                    l[t] = l[t] * corr + 1.0f;
                    acc[t][0] = acc[t][0] * corr + vj4.x;
                    acc[t][1] = acc[t][1] * corr + vj4.y;
                    acc[t][2] = acc[t][2] * corr + vj4.z;
                    acc[t][3] = acc[t][3] * corr + vj4.w;
                    mx[t] = s;
                }
            }
        }
        __syncthreads();
    }

    #pragma unroll
    for (int t = 0; t < 8; t++) {
        if (tok[t] < 0) continue;
        float inv = 1.0f / l[t];
        float a[4] = { acc[t][0] * inv, acc[t][1] * inv, acc[t][2] * inv, acc[t][3] * inv };
        __half hs[4], ls[4];
        #pragma unroll
        for (int j = 0; j < 4; j++) {
            hs[j] = __float2half_rn(a[j]);
            ls[j] = __float2half_rn(a[j] - __half2float(hs[j]));
        }
        size_t idx = (size_t)tok[t] * C_DIM + h * HD + lane * 4;
        *(uint2*)&g_ah[idx] = *(uint2*)hs;
        *(uint2*)&g_al[idx] = *(uint2*)ls;
    }
}

// ---------------- 6) y = x + coef[n,c] broadcast over HW -------------------
__global__ void k_add(const float* __restrict__ x, float* __restrict__ y) {
    const float4* x4 = (const float4*)x;
    float4* y4 = (float4*)y;
    const int total = N_TOK * C_DIM * (HW / 4);
    int stride = gridDim.x * blockDim.x;
    for (int i = blockIdx.x * blockDim.x + threadIdx.x; i < total; i += stride) {
        float c = g_coef[i >> 4];
        float4 v = x4[i];
        v.x += c; v.y += c; v.z += c; v.w += c;
        y4[i] = v;
    }
}

// ---------------- launch ---------------------------------------------------
extern "C" void kernel_launch(void* const* d_in, const int* in_sizes, int n_in,
                              void* d_out, int out_size) {
    const float* x          = (const float*)d_in[0];
    const int*   braw       = (const int*)  d_in[1];
    const float* ln_w       = (const float*)d_in[2];
    const float* ln_b       = (const float*)d_in[3];
    const float* in_proj_w  = (const float*)d_in[4];
    const float* in_proj_b  = (const float*)d_in[5];
    const float* out_proj_w = (const float*)d_in[6];
    const float* out_proj_b = (const float*)d_in[7];
    const float* gamma      = (const float*)d_in[8];
    float* y = (float*)d_out;

    __half *p_fh, *p_fl, *p_wq, *p_wo, *p_ah, *p_al;
    float *p_qkv, *p_coef;
    cudaGetSymbolAddress((void**)&p_fh,  g_fh);
    cudaGetSymbolAddress((void**)&p_fl,  g_fl);
    cudaGetSymbolAddress((void**)&p_wq,  g_wq);
    cudaGetSymbolAddress((void**)&p_wo,  g_wo);
    cudaGetSymbolAddress((void**)&p_ah,  g_ah);
    cudaGetSymbolAddress((void**)&p_al,  g_al);
    cudaGetSymbolAddress((void**)&p_qkv, g_qkv);
    cudaGetSymbolAddress((void**)&p_coef, g_coef);

    k_convert<<<8, 256>>>(braw);
    k_groups <<<8, 256>>>();
    k_mean   <<<65536, 256>>>(x);
    k_ln     <<<N_TOK, 256>>>(ln_w, ln_b);
    k_half   <<<3072, 256>>>(in_proj_w,  p_wq, 3 * C_DIM * C_DIM / 4);
    k_half   <<<1024, 256>>>(out_proj_w, p_wo, C_DIM * C_DIM / 4);
    k_hgemm  <<<dim3(24, 16), 256>>>(p_fh, p_fl, p_wq, in_proj_b, p_qkv,
                                     3 * C_DIM, 0, nullptr);
    k_attn   <<<NHEAD * NGRP * QCH, 256>>>();
    k_hgemm  <<<dim3(8, 16), 256>>>(p_ah, p_al, p_wo, out_proj_b, p_coef,
                                    C_DIM, 1, gamma);
    k_add    <<<32768, 256>>>(x, y);
}